// round 12
// baseline (speedup 1.0000x reference)
#include <cuda_runtime.h>

#define T_STEPS 32768
#define DIM     256
#define HID     64
#define G3      192      // 3*HID
#define JJ      1024     // J*J
#define CH      4        // scan prefetch chunk
#define TB      32       // t-rows per gi tile / flag granularity
#define NTB     (T_STEPS / TB)   // 1024
#define NBLK    148      // one block per SM (forced by smem)
#define NWORK   (NBLK - 1)
#define SMEM_FORCE (120 * 1024)

// Scratch (no runtime allocation allowed)
__device__ float g_gi[(T_STEPS + CH) * G3];   // padded for prefetch overrun
__device__ float g_hs[T_STEPS * HID];
__device__ unsigned g_flags[NTB + 8];         // [NTB..] sentinels = 1

typedef unsigned long long u64;

// ---------------- helpers ----------------
__device__ __forceinline__ u64 pack2(float lo, float hi) {
    u64 r; asm("mov.b64 %0, {%1, %2};" : "=l"(r) : "f"(lo), "f"(hi)); return r;
}
__device__ __forceinline__ void unpack2(u64 v, float& lo, float& hi) {
    asm("mov.b64 {%0, %1}, %2;" : "=f"(lo), "=f"(hi) : "l"(v));
}
__device__ __forceinline__ u64 fma2(u64 a, u64 b, u64 c) {
    u64 d; asm("fma.rn.f32x2 %0, %1, %2, %3;" : "=l"(d) : "l"(a), "l"(b), "l"(c)); return d;
}
__device__ __forceinline__ u64 add2(u64 a, u64 b) {
    u64 d; asm("add.rn.f32x2 %0, %1, %2;" : "=l"(d) : "l"(a), "l"(b)); return d;
}
__device__ __forceinline__ float red2(u64 v) { float a, b; unpack2(v, a, b); return a + b; }

__device__ __forceinline__ float ex2f(float x)  { float r; asm("ex2.approx.f32 %0, %1;"  : "=f"(r) : "f"(x)); return r; }
__device__ __forceinline__ float rcpf(float x)  { float r; asm("rcp.approx.f32 %0, %1;"  : "=f"(r) : "f"(x)); return r; }
__device__ __forceinline__ float tanhmu(float x){ float r; asm("tanh.approx.f32 %0, %1;" : "=f"(r) : "f"(x)); return r; }

__device__ __forceinline__ unsigned ld_acq(const unsigned* p) {
    unsigned v; asm volatile("ld.acquire.gpu.global.u32 %0, [%1];" : "=r"(v) : "l"(p) : "memory"); return v;
}
__device__ __forceinline__ void st_rel(unsigned* p, unsigned v) {
    asm volatile("st.release.gpu.global.u32 [%0], %1;" :: "l"(p), "r"(v) : "memory");
}

#define NL2E (-1.44269504088896340736f)

// =====================================================================
__global__ void reset_kernel() {
    int i = blockIdx.x * blockDim.x + threadIdx.x;
    if (i < NTB + 8) g_flags[i] = (i >= NTB) ? 1u : 0u;
}

// =====================================================================
// Fused kernel, 148 blocks x 192 threads, 1 block/SM (120KB dyn smem).
// Block 0  : GRU scan (warps 0-3 active; R4-proven step structure).
// Blocks 1+: gi tiles (32 t-rows), strided by 147, flag release per tile.
// =====================================================================
extern __shared__ char dyn_smem[];   // reservation only (forces exclusivity)

__global__ __launch_bounds__(192) void fused_kernel(const float* __restrict__ states,
                                                    const float* __restrict__ h0,
                                                    const float* __restrict__ w_ih,
                                                    const float* __restrict__ w_hh,
                                                    const float* __restrict__ b_ih,
                                                    const float* __restrict__ b_hh,
                                                    float* __restrict__ h_final) {
    __shared__ float xs[32][36];                  // gi x-tile
    __shared__ __align__(16) float hbuf[2][HID];  // scan h double buffer
    const int tid = threadIdx.x;

    if (blockIdx.x != 0) {
        // ---------------- gi worker ----------------
        const int g = tid;
        const float* wrow = w_ih + (size_t)g * DIM;
        const bool rz = (g < 128);
        const float bb = b_ih[g] + (rz ? b_hh[g] : 0.0f);
        const float sc = rz ? NL2E : 1.0f;

        for (int tb = blockIdx.x - 1; tb < NTB; tb += NWORK) {
            const int t0 = tb * TB;
            u64 acc[16];
#pragma unroll
            for (int q = 0; q < 16; q++) acc[q] = 0ULL;

            for (int d0 = 0; d0 < DIM; d0 += 32) {
                __syncthreads();
                for (int i = tid; i < 1024; i += 192) {
                    int dd = i & 31, tt = i >> 5;
                    xs[dd][tt] = states[(size_t)(t0 + tt) * (DIM + 3) + d0 + dd];
                }
                __syncthreads();

                float wv[32];
#pragma unroll
                for (int dd = 0; dd < 32; dd++) wv[dd] = wrow[d0 + dd];
#pragma unroll
                for (int dd = 0; dd < 32; dd++) {
                    u64 wp = pack2(wv[dd], wv[dd]);
                    const float4* xr = (const float4*)xs[dd];
#pragma unroll
                    for (int q = 0; q < 8; q++) {
                        float4 v = xr[q];
                        acc[2 * q + 0] = fma2(pack2(v.x, v.y), wp, acc[2 * q + 0]);
                        acc[2 * q + 1] = fma2(pack2(v.z, v.w), wp, acc[2 * q + 1]);
                    }
                }
            }
#pragma unroll
            for (int q = 0; q < 16; q++) {
                float a, c; unpack2(acc[q], a, c);
                g_gi[(size_t)(t0 + 2 * q + 0) * G3 + g] = sc * (a + bb);
                g_gi[(size_t)(t0 + 2 * q + 1) * G3 + g] = sc * (c + bb);
            }
            __syncthreads();
            if (tid == 0) st_rel(&g_flags[tb], 1u);
        }
        return;
    }

    // ---------------- scan (block 0): R4 structure, warps 0-3 active ----------------
    const int w    = tid >> 5;
    const int lane = tid & 31;
    const int m    = lane >> 1;
    const int j    = w * 16 + m;
    const int half = lane & 1;           // 0: k 0..31, 1: k 32..63
    const bool act = (tid < 128);

    u64 wr[16], wz[16], wn[16];
    u64 bn_init = 0ULL;
    float hcur = 0.0f;
    const float *gr = 0, *gz = 0, *gn = 0;

    if (act) {
        const u64* pr = (const u64*)(w_hh + (size_t)j * HID)         + half * 16;
        const u64* pz = (const u64*)(w_hh + (size_t)(64 + j) * HID)  + half * 16;
        const u64* pn = (const u64*)(w_hh + (size_t)(128 + j) * HID) + half * 16;
#pragma unroll
        for (int k = 0; k < 16; k++) { wr[k] = pr[k]; wz[k] = pz[k]; wn[k] = pn[k]; }
        const float bn = b_hh[128 + j];
        bn_init = half ? 0ULL : pack2(bn, 0.0f);
        hcur = h0[j];
        if (tid < HID) hbuf[0][tid] = h0[tid];
        gr = g_gi + j; gz = g_gi + 64 + j; gn = g_gi + 128 + j;
    }

    // tile 0 ready, first prefetch
    while (ld_acq(&g_flags[0]) == 0) {}
    float grn[CH], gzn[CH], gnn[CH];
    if (act) {
#pragma unroll
        for (int k = 0; k < CH; k++) {
            grn[k] = __ldcg(gr + (size_t)k * G3);
            gzn[k] = __ldcg(gz + (size_t)k * G3);
            gnn[k] = __ldcg(gn + (size_t)k * G3);
        }
    }
    unsigned fnext = ld_acq(&g_flags[1]);
    __syncthreads();

    for (int b = 0; b < NTB; b++) {
        // guarantee tile b+1 (chunk 7's prefetch crosses into it)
        if (fnext == 0) { while (ld_acq(&g_flags[b + 1]) == 0) {} }
        fnext = ld_acq(&g_flags[b + 2]);           // sentinel-padded

#pragma unroll 1
        for (int c = 0; c < TB / CH; c++) {
            const int s0 = b * TB + c * CH;
            float grc[CH], gzc[CH], gnc[CH];
            if (act) {
#pragma unroll
                for (int k = 0; k < CH; k++) { grc[k] = grn[k]; gzc[k] = gzn[k]; gnc[k] = gnn[k]; }
                const size_t nb = (size_t)(s0 + CH) * G3;
#pragma unroll
                for (int k = 0; k < CH; k++) {
                    grn[k] = __ldcg(gr + nb + (size_t)k * G3);
                    gzn[k] = __ldcg(gz + nb + (size_t)k * G3);
                    gnn[k] = __ldcg(gn + nb + (size_t)k * G3);
                }
            }

#pragma unroll
            for (int ss = 0; ss < CH; ss++) {
                if (act) {
                    const int p = ss & 1;
                    const ulonglong2* hp = (const ulonglong2*)(hbuf[p] + half * 32);
                    ulonglong2 hq[8];
#pragma unroll
                    for (int q = 0; q < 8; q++) hq[q] = hp[q];

                    // --- r phase ---
                    u64 a0 = 0, a1 = 0;
#pragma unroll
                    for (int q = 0; q < 8; q++) {
                        a0 = fma2(wr[2 * q],     hq[q].x, a0);
                        a1 = fma2(wr[2 * q + 1], hq[q].y, a1);
                    }
                    float sr = red2(add2(a0, a1));
                    sr += __shfl_xor_sync(0xffffffffu, sr, 1);
                    const float r = rcpf(1.0f + ex2f(fmaf(sr, NL2E, grc[ss])));

                    // --- z phase ---
                    u64 b0 = 0, b1 = 0;
#pragma unroll
                    for (int q = 0; q < 8; q++) {
                        b0 = fma2(wz[2 * q],     hq[q].x, b0);
                        b1 = fma2(wz[2 * q + 1], hq[q].y, b1);
                    }
                    float sz = red2(add2(b0, b1));
                    sz += __shfl_xor_sync(0xffffffffu, sz, 1);
                    const float z = rcpf(1.0f + ex2f(fmaf(sz, NL2E, gzc[ss])));

                    // --- n phase ---
                    u64 c0 = bn_init, c1 = 0;
#pragma unroll
                    for (int q = 0; q < 8; q++) {
                        c0 = fma2(wn[2 * q],     hq[q].x, c0);
                        c1 = fma2(wn[2 * q + 1], hq[q].y, c1);
                    }
                    float sn = red2(add2(c0, c1));
                    sn += __shfl_xor_sync(0xffffffffu, sn, 1);
                    const float n = tanhmu(fmaf(r, sn, gnc[ss]));

                    const float hnew = fmaf(z, hcur - n, n);
                    hcur = hnew;

                    if (half) {
                        hbuf[p ^ 1][j] = hnew;
                        g_hs[(size_t)(s0 + ss) * HID + j] = hnew;
                    }
                }
                __syncthreads();
            }
        }
    }
    if (act && half) h_final[j] = hcur;
}

// =====================================================================
// Kernel 3: logits[t,o] = mask[o] ? hs[t,:]·w_out[o,:] + b_out[o] : -1e9
// =====================================================================
__global__ __launch_bounds__(256) void out_kernel(const float* __restrict__ w_out,
                                                  const float* __restrict__ b_out,
                                                  const int* __restrict__ mask,
                                                  float* __restrict__ out) {
    __shared__ float hs_sh[64][68];
    __shared__ float w_sh[64][68];

    const int tid = threadIdx.x;
    const int t0  = blockIdx.x * 64;
    const int o0  = blockIdx.y * 64;

#pragma unroll
    for (int q = 0; q < 4; q++) {
        int i  = tid + q * 256;
        int rr = i >> 4;
        int kq = i & 15;
        float4 v = *(const float4*)(g_hs + (size_t)(t0 + rr) * HID + kq * 4);
        hs_sh[kq * 4 + 0][rr] = v.x;
        hs_sh[kq * 4 + 1][rr] = v.y;
        hs_sh[kq * 4 + 2][rr] = v.z;
        hs_sh[kq * 4 + 3][rr] = v.w;
        float4 wv = *(const float4*)(w_out + (size_t)(o0 + rr) * HID + kq * 4);
        w_sh[kq * 4 + 0][rr] = wv.x;
        w_sh[kq * 4 + 1][rr] = wv.y;
        w_sh[kq * 4 + 2][rr] = wv.z;
        w_sh[kq * 4 + 3][rr] = wv.w;
    }
    __syncthreads();

    const int oo0 = (tid & 15) * 4;
    const int tt0 = (tid >> 4) * 4;

    float acc[4][4];
#pragma unroll
    for (int i = 0; i < 4; i++)
#pragma unroll
        for (int jj2 = 0; jj2 < 4; jj2++) acc[i][jj2] = 0.0f;

#pragma unroll
    for (int k = 0; k < 64; k++) {
        float4 a = *(const float4*)&hs_sh[k][tt0];
        float4 b = *(const float4*)&w_sh[k][oo0];
        float av[4] = {a.x, a.y, a.z, a.w};
        float bv[4] = {b.x, b.y, b.z, b.w};
#pragma unroll
        for (int i = 0; i < 4; i++)
#pragma unroll
            for (int jj2 = 0; jj2 < 4; jj2++) acc[i][jj2] += av[i] * bv[jj2];
    }

    float bo[4]; int mk[4];
#pragma unroll
    for (int jj2 = 0; jj2 < 4; jj2++) {
        int o = o0 + oo0 + jj2;
        bo[jj2] = b_out[o];
        mk[jj2] = mask[o];
    }
#pragma unroll
    for (int i = 0; i < 4; i++) {
        float r4[4];
#pragma unroll
        for (int jj2 = 0; jj2 < 4; jj2++) {
            float v = acc[i][jj2] + bo[jj2];
            r4[jj2] = (mk[jj2] == 0) ? -1000000000.0f : v;
        }
        float4 res = make_float4(r4[0], r4[1], r4[2], r4[3]);
        *(float4*)(out + (size_t)(t0 + tt0 + i) * JJ + o0 + oo0) = res;
    }
}

// =====================================================================
extern "C" void kernel_launch(void* const* d_in, const int* in_sizes, int n_in,
                              void* d_out, int out_size) {
    const float* states = (const float*)d_in[0];
    const float* h0     = (const float*)d_in[1];
    const float* w_ih   = (const float*)d_in[2];
    const float* w_hh   = (const float*)d_in[3];
    const float* b_ih   = (const float*)d_in[4];
    const float* b_hh   = (const float*)d_in[5];
    const float* w_out  = (const float*)d_in[6];
    const float* b_out  = (const float*)d_in[7];
    const int*   mask   = (const int*)d_in[8];
    float* out = (float*)d_out;

    cudaFuncSetAttribute(fused_kernel,
                         cudaFuncAttributeMaxDynamicSharedMemorySize, SMEM_FORCE);

    reset_kernel<<<(NTB + 8 + 255) / 256, 256>>>();
    fused_kernel<<<NBLK, 192, SMEM_FORCE>>>(states, h0, w_ih, w_hh, b_ih, b_hh,
                                            out + (size_t)T_STEPS * JJ);
    out_kernel<<<dim3(512, 16), 256>>>(w_out, b_out, mask, out);
}

// round 14
// speedup vs baseline: 1.2637x; 1.2637x over previous
#include <cuda_runtime.h>

#define T_STEPS 32768
#define DIM     256
#define HID     64
#define G3      192      // 3*HID
#define JJ      1024     // J*J
#define CH      8        // scan prefetch chunk

// Scratch (no runtime allocation allowed)
__device__ float g_gi[(T_STEPS + CH) * G3];   // padded for prefetch overrun
__device__ float g_hs[T_STEPS * HID];

typedef unsigned long long u64;

// ---------------- helpers ----------------
__device__ __forceinline__ u64 pack2(float lo, float hi) {
    u64 r; asm("mov.b64 %0, {%1, %2};" : "=l"(r) : "f"(lo), "f"(hi)); return r;
}
__device__ __forceinline__ void unpack2(u64 v, float& lo, float& hi) {
    asm("mov.b64 {%0, %1}, %2;" : "=f"(lo), "=f"(hi) : "l"(v));
}
__device__ __forceinline__ u64 fma2(u64 a, u64 b, u64 c) {
    u64 d; asm("fma.rn.f32x2 %0, %1, %2, %3;" : "=l"(d) : "l"(a), "l"(b), "l"(c)); return d;
}
__device__ __forceinline__ u64 add2(u64 a, u64 b) {
    u64 d; asm("add.rn.f32x2 %0, %1, %2;" : "=l"(d) : "l"(a), "l"(b)); return d;
}
__device__ __forceinline__ float red2(u64 v) { float a, b; unpack2(v, a, b); return a + b; }

__device__ __forceinline__ float ex2f(float x)  { float r; asm("ex2.approx.f32 %0, %1;"  : "=f"(r) : "f"(x)); return r; }
__device__ __forceinline__ float rcpf(float x)  { float r; asm("rcp.approx.f32 %0, %1;"  : "=f"(r) : "f"(x)); return r; }
__device__ __forceinline__ float tanhmu(float x){ float r; asm("tanh.approx.f32 %0, %1;" : "=f"(r) : "f"(x)); return r; }

#define NL2E (-1.44269504088896340736f)

// =====================================================================
// Kernel 1: gi precompute (R4-proven, 269us measured).
//   g < 128  (r,z rows): gi = NL2E * (x·w_ih[g] + b_ih[g] + b_hh[g])
//   g >= 128 (n rows)  : gi =         x·w_ih[g] + b_ih[g]
// =====================================================================
__global__ __launch_bounds__(192) void gi_kernel(const float* __restrict__ states,
                                                 const float* __restrict__ w_ih,
                                                 const float* __restrict__ b_ih,
                                                 const float* __restrict__ b_hh) {
    __shared__ float xs[32][36];
    const int tid = threadIdx.x;
    const int t0  = blockIdx.x * 32;

    u64 acc[16];
#pragma unroll
    for (int q = 0; q < 16; q++) acc[q] = 0ULL;

    const float* wrow = w_ih + (size_t)tid * DIM;

    for (int d0 = 0; d0 < DIM; d0 += 32) {
        __syncthreads();
        for (int i = tid; i < 1024; i += 192) {
            int dd = i & 31, tt = i >> 5;
            xs[dd][tt] = states[(size_t)(t0 + tt) * (DIM + 3) + d0 + dd];
        }
        __syncthreads();

        float wv[32];
#pragma unroll
        for (int dd = 0; dd < 32; dd++) wv[dd] = wrow[d0 + dd];

#pragma unroll
        for (int dd = 0; dd < 32; dd++) {
            u64 wp = pack2(wv[dd], wv[dd]);
            const float4* xr = (const float4*)xs[dd];
#pragma unroll
            for (int q = 0; q < 8; q++) {
                float4 v = xr[q];
                acc[2 * q + 0] = fma2(pack2(v.x, v.y), wp, acc[2 * q + 0]);
                acc[2 * q + 1] = fma2(pack2(v.z, v.w), wp, acc[2 * q + 1]);
            }
        }
    }

    const bool rz = (tid < 128);
    const float b = b_ih[tid] + (rz ? b_hh[tid] : 0.0f);
    const float s = rz ? NL2E : 1.0f;
#pragma unroll
    for (int q = 0; q < 16; q++) {
        float a, c; unpack2(acc[q], a, c);
        g_gi[(size_t)(t0 + 2 * q + 0) * G3 + tid] = s * (a + b);
        g_gi[(size_t)(t0 + 2 * q + 1) * G3 + tid] = s * (c + b);
    }
}

// =====================================================================
// Kernel 2: sequential GRU scan. ONE block, 128 threads (4 warps).
// R4-proven structure: lane pair (2m,2m+1) owns j = warp*16+m, split by
// k-half; phases r -> z -> n, each red2 + one shfl.xor(1); activations
// computed redundantly in both lanes. One __syncthreads per step.
// CH=8 halves per-step prefetch/loop overhead vs R4.
// =====================================================================
__global__ __launch_bounds__(128, 1) void scan_kernel(const float* __restrict__ h0,
                                                      const float* __restrict__ w_hh,
                                                      const float* __restrict__ b_hh,
                                                      float* __restrict__ h_final) {
    __shared__ __align__(16) float hbuf[2][HID];

    const int tid  = threadIdx.x;
    const int w    = tid >> 5;
    const int lane = tid & 31;
    const int m    = lane >> 1;
    const int j    = w * 16 + m;
    const int half = lane & 1;               // 0: k 0..31, 1: k 32..63

    u64 wr[16], wz[16], wn[16];
    {
        const u64* pr = (const u64*)(w_hh + (size_t)j * HID)         + half * 16;
        const u64* pz = (const u64*)(w_hh + (size_t)(64 + j) * HID)  + half * 16;
        const u64* pn = (const u64*)(w_hh + (size_t)(128 + j) * HID) + half * 16;
#pragma unroll
        for (int k = 0; k < 16; k++) { wr[k] = pr[k]; wz[k] = pz[k]; wn[k] = pn[k]; }
    }
    const float bn = b_hh[128 + j];
    const u64 bn_init = half ? 0ULL : pack2(bn, 0.0f);

    if (tid < HID) hbuf[0][tid] = h0[tid];
    float hcur = h0[j];

    const float* gr = g_gi + j;
    const float* gz = g_gi + 64 + j;
    const float* gn = g_gi + 128 + j;

    float grn[CH], gzn[CH], gnn[CH];
#pragma unroll
    for (int k = 0; k < CH; k++) {
        grn[k] = __ldcg(gr + (size_t)k * G3);
        gzn[k] = __ldcg(gz + (size_t)k * G3);
        gnn[k] = __ldcg(gn + (size_t)k * G3);
    }
    __syncthreads();

    for (int s0 = 0; s0 < T_STEPS; s0 += CH) {
        float grc[CH], gzc[CH], gnc[CH];
#pragma unroll
        for (int k = 0; k < CH; k++) { grc[k] = grn[k]; gzc[k] = gzn[k]; gnc[k] = gnn[k]; }
        {   // prefetch next chunk (padded tail is harmless)
            const size_t nb = (size_t)(s0 + CH) * G3;
#pragma unroll
            for (int k = 0; k < CH; k++) {
                grn[k] = __ldcg(gr + nb + (size_t)k * G3);
                gzn[k] = __ldcg(gz + nb + (size_t)k * G3);
                gnn[k] = __ldcg(gn + nb + (size_t)k * G3);
            }
        }

#pragma unroll
        for (int ss = 0; ss < CH; ss++) {
            const int p = ss & 1;
            const ulonglong2* hp = (const ulonglong2*)(hbuf[p] + half * 32);
            ulonglong2 hq[8];
#pragma unroll
            for (int q = 0; q < 8; q++) hq[q] = hp[q];

            // --- r phase: shfl + MUFU tail overlaps z/n FMA issue ---
            u64 a0 = 0, a1 = 0;
#pragma unroll
            for (int q = 0; q < 8; q++) {
                a0 = fma2(wr[2 * q],     hq[q].x, a0);
                a1 = fma2(wr[2 * q + 1], hq[q].y, a1);
            }
            float sr = red2(add2(a0, a1));
            sr += __shfl_xor_sync(0xffffffffu, sr, 1);
            const float r = rcpf(1.0f + ex2f(fmaf(sr, NL2E, grc[ss])));

            // --- z phase ---
            u64 b0 = 0, b1 = 0;
#pragma unroll
            for (int q = 0; q < 8; q++) {
                b0 = fma2(wz[2 * q],     hq[q].x, b0);
                b1 = fma2(wz[2 * q + 1], hq[q].y, b1);
            }
            float sz = red2(add2(b0, b1));
            sz += __shfl_xor_sync(0xffffffffu, sz, 1);
            const float z = rcpf(1.0f + ex2f(fmaf(sz, NL2E, gzc[ss])));

            // --- n phase ---
            u64 c0 = bn_init, c1 = 0;
#pragma unroll
            for (int q = 0; q < 8; q++) {
                c0 = fma2(wn[2 * q],     hq[q].x, c0);
                c1 = fma2(wn[2 * q + 1], hq[q].y, c1);
            }
            float sn = red2(add2(c0, c1));
            sn += __shfl_xor_sync(0xffffffffu, sn, 1);
            const float n = tanhmu(fmaf(r, sn, gnc[ss]));

            const float hnew = fmaf(z, hcur - n, n);   // n + z*(hcur-n)
            hcur = hnew;

            if (half) {
                hbuf[p ^ 1][j] = hnew;
                g_hs[(size_t)(s0 + ss) * HID + j] = hnew;
            }
            __syncthreads();
        }
    }
    if (half) h_final[j] = hcur;
}

// =====================================================================
// Kernel 3: logits[t,o] = mask[o] ? hs[t,:]·w_out[o,:] + b_out[o] : -1e9
// =====================================================================
__global__ __launch_bounds__(256) void out_kernel(const float* __restrict__ w_out,
                                                  const float* __restrict__ b_out,
                                                  const int* __restrict__ mask,
                                                  float* __restrict__ out) {
    __shared__ float hs_sh[64][68];
    __shared__ float w_sh[64][68];

    const int tid = threadIdx.x;
    const int t0  = blockIdx.x * 64;
    const int o0  = blockIdx.y * 64;

#pragma unroll
    for (int q = 0; q < 4; q++) {
        int i  = tid + q * 256;
        int rr = i >> 4;
        int kq = i & 15;
        float4 v = *(const float4*)(g_hs + (size_t)(t0 + rr) * HID + kq * 4);
        hs_sh[kq * 4 + 0][rr] = v.x;
        hs_sh[kq * 4 + 1][rr] = v.y;
        hs_sh[kq * 4 + 2][rr] = v.z;
        hs_sh[kq * 4 + 3][rr] = v.w;
        float4 wv = *(const float4*)(w_out + (size_t)(o0 + rr) * HID + kq * 4);
        w_sh[kq * 4 + 0][rr] = wv.x;
        w_sh[kq * 4 + 1][rr] = wv.y;
        w_sh[kq * 4 + 2][rr] = wv.z;
        w_sh[kq * 4 + 3][rr] = wv.w;
    }
    __syncthreads();

    const int oo0 = (tid & 15) * 4;
    const int tt0 = (tid >> 4) * 4;

    float acc[4][4];
#pragma unroll
    for (int i = 0; i < 4; i++)
#pragma unroll
        for (int jj2 = 0; jj2 < 4; jj2++) acc[i][jj2] = 0.0f;

#pragma unroll
    for (int k = 0; k < 64; k++) {
        float4 a = *(const float4*)&hs_sh[k][tt0];
        float4 b = *(const float4*)&w_sh[k][oo0];
        float av[4] = {a.x, a.y, a.z, a.w};
        float bv[4] = {b.x, b.y, b.z, b.w};
#pragma unroll
        for (int i = 0; i < 4; i++)
#pragma unroll
            for (int jj2 = 0; jj2 < 4; jj2++) acc[i][jj2] += av[i] * bv[jj2];
    }

    float bo[4]; int mk[4];
#pragma unroll
    for (int jj2 = 0; jj2 < 4; jj2++) {
        int o = o0 + oo0 + jj2;
        bo[jj2] = b_out[o];
        mk[jj2] = mask[o];
    }
#pragma unroll
    for (int i = 0; i < 4; i++) {
        float r4[4];
#pragma unroll
        for (int jj2 = 0; jj2 < 4; jj2++) {
            float v = acc[i][jj2] + bo[jj2];
            r4[jj2] = (mk[jj2] == 0) ? -1000000000.0f : v;
        }
        float4 res = make_float4(r4[0], r4[1], r4[2], r4[3]);
        *(float4*)(out + (size_t)(t0 + tt0 + i) * JJ + o0 + oo0) = res;
    }
}

// =====================================================================
extern "C" void kernel_launch(void* const* d_in, const int* in_sizes, int n_in,
                              void* d_out, int out_size) {
    const float* states = (const float*)d_in[0];
    const float* h0     = (const float*)d_in[1];
    const float* w_ih   = (const float*)d_in[2];
    const float* w_hh   = (const float*)d_in[3];
    const float* b_ih   = (const float*)d_in[4];
    const float* b_hh   = (const float*)d_in[5];
    const float* w_out  = (const float*)d_in[6];
    const float* b_out  = (const float*)d_in[7];
    const int*   mask   = (const int*)d_in[8];
    float* out = (float*)d_out;

    gi_kernel<<<1024, 192>>>(states, w_ih, b_ih, b_hh);
    scan_kernel<<<1, 128>>>(h0, w_hh, b_hh, out + (size_t)T_STEPS * JJ);
    out_kernel<<<dim3(512, 16), 256>>>(w_out, b_out, mask, out);
}

// round 15
// speedup vs baseline: 1.3430x; 1.0627x over previous
#include <cuda_runtime.h>

#define T_STEPS 32768
#define DIM     256
#define HID     64
#define G3      192      // 3*HID
#define JJ      1024     // J*J
#define CH      4        // scan prefetch chunk (paired: 2*CH lookahead fits pad)

// Scratch (no runtime allocation allowed)
__device__ float g_gi[(T_STEPS + 2 * CH) * G3];   // padded for prefetch overrun
__device__ float g_hs[T_STEPS * HID];

typedef unsigned long long u64;

// ---------------- helpers ----------------
__device__ __forceinline__ u64 pack2(float lo, float hi) {
    u64 r; asm("mov.b64 %0, {%1, %2};" : "=l"(r) : "f"(lo), "f"(hi)); return r;
}
__device__ __forceinline__ void unpack2(u64 v, float& lo, float& hi) {
    asm("mov.b64 {%0, %1}, %2;" : "=f"(lo), "=f"(hi) : "l"(v));
}
__device__ __forceinline__ u64 fma2(u64 a, u64 b, u64 c) {
    u64 d; asm("fma.rn.f32x2 %0, %1, %2, %3;" : "=l"(d) : "l"(a), "l"(b), "l"(c)); return d;
}
__device__ __forceinline__ u64 add2(u64 a, u64 b) {
    u64 d; asm("add.rn.f32x2 %0, %1, %2;" : "=l"(d) : "l"(a), "l"(b)); return d;
}
__device__ __forceinline__ u64 mul2(u64 a, u64 b) {
    u64 d; asm("mul.rn.f32x2 %0, %1, %2;" : "=l"(d) : "l"(a), "l"(b)); return d;
}
__device__ __forceinline__ float red2(u64 v) { float a, b; unpack2(v, a, b); return a + b; }

__device__ __forceinline__ float tanhmu(float x){ float r; asm("tanh.approx.f32 %0, %1;" : "=f"(r) : "f"(x)); return r; }

// =====================================================================
// Kernel 1: gi precompute.
//   g < 128  (r,z rows): gi = 0.5 * (x·w_ih[g] + b_ih[g] + b_hh[g])   [tanh-sigmoid form]
//   g >= 128 (n rows)  : gi =        x·w_ih[g] + b_ih[g]
// =====================================================================
__global__ __launch_bounds__(192) void gi_kernel(const float* __restrict__ states,
                                                 const float* __restrict__ w_ih,
                                                 const float* __restrict__ b_ih,
                                                 const float* __restrict__ b_hh) {
    __shared__ float xs[32][36];
    const int tid = threadIdx.x;
    const int t0  = blockIdx.x * 32;

    u64 acc[16];
#pragma unroll
    for (int q = 0; q < 16; q++) acc[q] = 0ULL;

    const float* wrow = w_ih + (size_t)tid * DIM;

    for (int d0 = 0; d0 < DIM; d0 += 32) {
        __syncthreads();
        for (int i = tid; i < 1024; i += 192) {
            int dd = i & 31, tt = i >> 5;
            xs[dd][tt] = states[(size_t)(t0 + tt) * (DIM + 3) + d0 + dd];
        }
        __syncthreads();

        float wv[32];
#pragma unroll
        for (int dd = 0; dd < 32; dd++) wv[dd] = wrow[d0 + dd];

#pragma unroll
        for (int dd = 0; dd < 32; dd++) {
            u64 wp = pack2(wv[dd], wv[dd]);
            const float4* xr = (const float4*)xs[dd];
#pragma unroll
            for (int q = 0; q < 8; q++) {
                float4 v = xr[q];
                acc[2 * q + 0] = fma2(pack2(v.x, v.y), wp, acc[2 * q + 0]);
                acc[2 * q + 1] = fma2(pack2(v.z, v.w), wp, acc[2 * q + 1]);
            }
        }
    }

    const bool rz = (tid < 128);
    const float b = b_ih[tid] + (rz ? b_hh[tid] : 0.0f);
    const float s = rz ? 0.5f : 1.0f;
#pragma unroll
    for (int q = 0; q < 16; q++) {
        float a, c; unpack2(acc[q], a, c);
        g_gi[(size_t)(t0 + 2 * q + 0) * G3 + tid] = s * (a + b);
        g_gi[(size_t)(t0 + 2 * q + 1) * G3 + tid] = s * (c + b);
    }
}

// =====================================================================
// Kernel 2: sequential GRU scan. ONE block, 128 threads (4 warps).
// R4-proven split: lane pair (2m,2m+1) owns j = warp*16+m, k-halved.
// All weights pre-halved in registers; sigmoids via tanh identity:
//   sigma(x) = 0.5*(1+tanh(x/2))
//   r never materialized: n_arg = (gn + S) + tr*S,  S = halved n-dot(+bn/2)
//   hnew = fma(n, B, A); A = fma(h/2, tz, h/2), B = fma(-1/2, tz, 1/2)
// gi double-buffered (ping-pong macro) to kill per-chunk reg copies.
// =====================================================================

#define SCAN_CHUNK(CR, CZ, CN, NR, NZ, NN, S0)                                   \
    do {                                                                          \
        const size_t nb_ = (size_t)((S0) + CH) * G3;                              \
        _Pragma("unroll")                                                         \
        for (int k = 0; k < CH; k++) {                                            \
            NR[k] = __ldcg(gr + nb_ + (size_t)k * G3);                            \
            NZ[k] = __ldcg(gz + nb_ + (size_t)k * G3);                            \
            NN[k] = __ldcg(gn + nb_ + (size_t)k * G3);                            \
        }                                                                         \
        _Pragma("unroll")                                                         \
        for (int ss = 0; ss < CH; ss++) {                                         \
            const int p = ss & 1;                                                 \
            const ulonglong2* hp = (const ulonglong2*)(hbuf[p] + half * 32);      \
            ulonglong2 hq[8];                                                     \
            _Pragma("unroll")                                                     \
            for (int q = 0; q < 8; q++) hq[q] = hp[q];                            \
            const float hc05 = 0.5f * hcur;                                       \
            /* r phase */                                                         \
            u64 a0 = 0, a1 = 0;                                                   \
            _Pragma("unroll")                                                     \
            for (int q = 0; q < 8; q++) {                                         \
                a0 = fma2(wr[2 * q],     hq[q].x, a0);                            \
                a1 = fma2(wr[2 * q + 1], hq[q].y, a1);                            \
            }                                                                     \
            float sr = red2(add2(a0, a1));                                        \
            sr += __shfl_xor_sync(0xffffffffu, sr, 1);                            \
            const float tr = tanhmu(sr + CR[ss]);                                 \
            /* z phase */                                                         \
            u64 b0 = 0, b1 = 0;                                                   \
            _Pragma("unroll")                                                     \
            for (int q = 0; q < 8; q++) {                                         \
                b0 = fma2(wz[2 * q],     hq[q].x, b0);                            \
                b1 = fma2(wz[2 * q + 1], hq[q].y, b1);                            \
            }                                                                     \
            float sz = red2(add2(b0, b1));                                        \
            sz += __shfl_xor_sync(0xffffffffu, sz, 1);                            \
            const float tz = tanhmu(sz + CZ[ss]);                                 \
            const float A_ = fmaf(hc05, tz, hc05);                                \
            const float B_ = fmaf(-0.5f, tz, 0.5f);                               \
            /* n phase */                                                         \
            u64 c0 = bn_init, c1 = 0;                                             \
            _Pragma("unroll")                                                     \
            for (int q = 0; q < 8; q++) {                                         \
                c0 = fma2(wn[2 * q],     hq[q].x, c0);                            \
                c1 = fma2(wn[2 * q + 1], hq[q].y, c1);                            \
            }                                                                     \
            float S_ = red2(add2(c0, c1));                                        \
            S_ += __shfl_xor_sync(0xffffffffu, S_, 1);                            \
            const float n_ = tanhmu(fmaf(tr, S_, CN[ss] + S_));                   \
            const float hnew = fmaf(n_, B_, A_);                                  \
            hcur = hnew;                                                          \
            if (half) {                                                           \
                hbuf[p ^ 1][j] = hnew;                                            \
                g_hs[(size_t)((S0) + ss) * HID + j] = hnew;                       \
            }                                                                     \
            __syncthreads();                                                      \
        }                                                                         \
    } while (0)

__global__ __launch_bounds__(128, 1) void scan_kernel(const float* __restrict__ h0,
                                                      const float* __restrict__ w_hh,
                                                      const float* __restrict__ b_hh,
                                                      float* __restrict__ h_final) {
    __shared__ __align__(16) float hbuf[2][HID];

    const int tid  = threadIdx.x;
    const int w    = tid >> 5;
    const int lane = tid & 31;
    const int m    = lane >> 1;
    const int j    = w * 16 + m;
    const int half = lane & 1;               // 0: k 0..31, 1: k 32..63

    // Weight half-rows in registers, pre-halved (tanh-sigmoid + 2rS identity)
    u64 wr[16], wz[16], wn[16];
    {
        const u64 h05 = pack2(0.5f, 0.5f);
        const u64* pr = (const u64*)(w_hh + (size_t)j * HID)         + half * 16;
        const u64* pz = (const u64*)(w_hh + (size_t)(64 + j) * HID)  + half * 16;
        const u64* pn = (const u64*)(w_hh + (size_t)(128 + j) * HID) + half * 16;
#pragma unroll
        for (int k = 0; k < 16; k++) {
            wr[k] = mul2(pr[k], h05);
            wz[k] = mul2(pz[k], h05);
            wn[k] = mul2(pn[k], h05);
        }
    }
    const float bn = b_hh[128 + j];
    const u64 bn_init = half ? 0ULL : pack2(0.5f * bn, 0.0f);   // bn/2 into S

    if (tid < HID) hbuf[0][tid] = h0[tid];
    float hcur = h0[j];

    const float* gr = g_gi + j;
    const float* gz = g_gi + 64 + j;
    const float* gn = g_gi + 128 + j;

    float gAr[CH], gAz[CH], gAn[CH];
    float gBr[CH], gBz[CH], gBn[CH];
#pragma unroll
    for (int k = 0; k < CH; k++) {
        gAr[k] = __ldcg(gr + (size_t)k * G3);
        gAz[k] = __ldcg(gz + (size_t)k * G3);
        gAn[k] = __ldcg(gn + (size_t)k * G3);
    }
    __syncthreads();

#pragma unroll 1
    for (int s0 = 0; s0 < T_STEPS; s0 += 2 * CH) {
        SCAN_CHUNK(gAr, gAz, gAn, gBr, gBz, gBn, s0);
        SCAN_CHUNK(gBr, gBz, gBn, gAr, gAz, gAn, s0 + CH);
    }
    if (half) h_final[j] = hcur;
}

// =====================================================================
// Kernel 3: logits[t,o] = mask[o] ? hs[t,:]·w_out[o,:] + b_out[o] : -1e9
// =====================================================================
__global__ __launch_bounds__(256) void out_kernel(const float* __restrict__ w_out,
                                                  const float* __restrict__ b_out,
                                                  const int* __restrict__ mask,
                                                  float* __restrict__ out) {
    __shared__ float hs_sh[64][68];
    __shared__ float w_sh[64][68];

    const int tid = threadIdx.x;
    const int t0  = blockIdx.x * 64;
    const int o0  = blockIdx.y * 64;

#pragma unroll
    for (int q = 0; q < 4; q++) {
        int i  = tid + q * 256;
        int rr = i >> 4;
        int kq = i & 15;
        float4 v = *(const float4*)(g_hs + (size_t)(t0 + rr) * HID + kq * 4);
        hs_sh[kq * 4 + 0][rr] = v.x;
        hs_sh[kq * 4 + 1][rr] = v.y;
        hs_sh[kq * 4 + 2][rr] = v.z;
        hs_sh[kq * 4 + 3][rr] = v.w;
        float4 wv = *(const float4*)(w_out + (size_t)(o0 + rr) * HID + kq * 4);
        w_sh[kq * 4 + 0][rr] = wv.x;
        w_sh[kq * 4 + 1][rr] = wv.y;
        w_sh[kq * 4 + 2][rr] = wv.z;
        w_sh[kq * 4 + 3][rr] = wv.w;
    }
    __syncthreads();

    const int oo0 = (tid & 15) * 4;
    const int tt0 = (tid >> 4) * 4;

    float acc[4][4];
#pragma unroll
    for (int i = 0; i < 4; i++)
#pragma unroll
        for (int jj2 = 0; jj2 < 4; jj2++) acc[i][jj2] = 0.0f;

#pragma unroll
    for (int k = 0; k < 64; k++) {
        float4 a = *(const float4*)&hs_sh[k][tt0];
        float4 b = *(const float4*)&w_sh[k][oo0];
        float av[4] = {a.x, a.y, a.z, a.w};
        float bv[4] = {b.x, b.y, b.z, b.w};
#pragma unroll
        for (int i = 0; i < 4; i++)
#pragma unroll
            for (int jj2 = 0; jj2 < 4; jj2++) acc[i][jj2] += av[i] * bv[jj2];
    }

    float bo[4]; int mk[4];
#pragma unroll
    for (int jj2 = 0; jj2 < 4; jj2++) {
        int o = o0 + oo0 + jj2;
        bo[jj2] = b_out[o];
        mk[jj2] = mask[o];
    }
#pragma unroll
    for (int i = 0; i < 4; i++) {
        float r4[4];
#pragma unroll
        for (int jj2 = 0; jj2 < 4; jj2++) {
            float v = acc[i][jj2] + bo[jj2];
            r4[jj2] = (mk[jj2] == 0) ? -1000000000.0f : v;
        }
        float4 res = make_float4(r4[0], r4[1], r4[2], r4[3]);
        *(float4*)(out + (size_t)(t0 + tt0 + i) * JJ + o0 + oo0) = res;
    }
}

// =====================================================================
extern "C" void kernel_launch(void* const* d_in, const int* in_sizes, int n_in,
                              void* d_out, int out_size) {
    const float* states = (const float*)d_in[0];
    const float* h0     = (const float*)d_in[1];
    const float* w_ih   = (const float*)d_in[2];
    const float* w_hh   = (const float*)d_in[3];
    const float* b_ih   = (const float*)d_in[4];
    const float* b_hh   = (const float*)d_in[5];
    const float* w_out  = (const float*)d_in[6];
    const float* b_out  = (const float*)d_in[7];
    const int*   mask   = (const int*)d_in[8];
    float* out = (float*)d_out;

    gi_kernel<<<1024, 192>>>(states, w_ih, b_ih, b_hh);
    scan_kernel<<<1, 128>>>(h0, w_hh, b_hh, out + (size_t)T_STEPS * JJ);
    out_kernel<<<dim3(512, 16), 256>>>(w_out, b_out, mask, out);
}

// round 16
// speedup vs baseline: 1.4065x; 1.0473x over previous
#include <cuda_runtime.h>

#define T_STEPS 32768
#define DIM     256
#define HID     64
#define G3      192      // 3*HID
#define JJ      1024     // J*J
#define CH      4        // scan prefetch chunk (paired: 2*CH lookahead fits pad)

// Scratch (no runtime allocation allowed)
__device__ float g_gi[(T_STEPS + 2 * CH) * G3];   // padded for prefetch overrun
__device__ float g_hs[T_STEPS * HID];

typedef unsigned long long u64;

// ---------------- helpers ----------------
__device__ __forceinline__ u64 pack2(float lo, float hi) {
    u64 r; asm("mov.b64 %0, {%1, %2};" : "=l"(r) : "f"(lo), "f"(hi)); return r;
}
__device__ __forceinline__ void unpack2(u64 v, float& lo, float& hi) {
    asm("mov.b64 {%0, %1}, %2;" : "=f"(lo), "=f"(hi) : "l"(v));
}
__device__ __forceinline__ u64 fma2(u64 a, u64 b, u64 c) {
    u64 d; asm("fma.rn.f32x2 %0, %1, %2, %3;" : "=l"(d) : "l"(a), "l"(b), "l"(c)); return d;
}
__device__ __forceinline__ u64 add2(u64 a, u64 b) {
    u64 d; asm("add.rn.f32x2 %0, %1, %2;" : "=l"(d) : "l"(a), "l"(b)); return d;
}
__device__ __forceinline__ u64 mul2(u64 a, u64 b) {
    u64 d; asm("mul.rn.f32x2 %0, %1, %2;" : "=l"(d) : "l"(a), "l"(b)); return d;
}
__device__ __forceinline__ float red2(u64 v) { float a, b; unpack2(v, a, b); return a + b; }

__device__ __forceinline__ float tanhmu(float x){ float r; asm("tanh.approx.f32 %0, %1;" : "=f"(r) : "f"(x)); return r; }

// =====================================================================
// Kernel 1: gi precompute.
//   g < 128  (r,z rows): gi = 0.5 * (x·w_ih[g] + b_ih[g] + b_hh[g])   [tanh-sigmoid form]
//   g >= 128 (n rows)  : gi =        x·w_ih[g] + b_ih[g]
// =====================================================================
__global__ __launch_bounds__(192) void gi_kernel(const float* __restrict__ states,
                                                 const float* __restrict__ w_ih,
                                                 const float* __restrict__ b_ih,
                                                 const float* __restrict__ b_hh) {
    __shared__ float xs[32][36];
    const int tid = threadIdx.x;
    const int t0  = blockIdx.x * 32;

    u64 acc[16];
#pragma unroll
    for (int q = 0; q < 16; q++) acc[q] = 0ULL;

    const float* wrow = w_ih + (size_t)tid * DIM;

    for (int d0 = 0; d0 < DIM; d0 += 32) {
        __syncthreads();
        for (int i = tid; i < 1024; i += 192) {
            int dd = i & 31, tt = i >> 5;
            xs[dd][tt] = states[(size_t)(t0 + tt) * (DIM + 3) + d0 + dd];
        }
        __syncthreads();

        float wv[32];
#pragma unroll
        for (int dd = 0; dd < 32; dd++) wv[dd] = wrow[d0 + dd];

#pragma unroll
        for (int dd = 0; dd < 32; dd++) {
            u64 wp = pack2(wv[dd], wv[dd]);
            const float4* xr = (const float4*)xs[dd];
#pragma unroll
            for (int q = 0; q < 8; q++) {
                float4 v = xr[q];
                acc[2 * q + 0] = fma2(pack2(v.x, v.y), wp, acc[2 * q + 0]);
                acc[2 * q + 1] = fma2(pack2(v.z, v.w), wp, acc[2 * q + 1]);
            }
        }
    }

    const bool rz = (tid < 128);
    const float b = b_ih[tid] + (rz ? b_hh[tid] : 0.0f);
    const float s = rz ? 0.5f : 1.0f;
#pragma unroll
    for (int q = 0; q < 16; q++) {
        float a, c; unpack2(acc[q], a, c);
        g_gi[(size_t)(t0 + 2 * q + 0) * G3 + tid] = s * (a + b);
        g_gi[(size_t)(t0 + 2 * q + 1) * G3 + tid] = s * (c + b);
    }
}

// =====================================================================
// Kernel 2: sequential GRU scan. ONE block, 128 threads (4 warps).
// Lane pair (2m,2m+1) owns j = warp*16+m, k-halved. NEW: the three gate
// dots are INTERLEAVED in one loop (single dense FMA block), then ONE
// merged tail: 3 reds -> 3 back-to-back shfls -> activations, so the
// three chain latencies mutually overlap. tanh-sigmoid identity:
//   sigma(x)=0.5*(1+tanh(x/2)); weights pre-halved; r never materialized
//   (n_arg = (gn+S) + tr*S); hnew = fma(n,B,A).
// =====================================================================

#define SCAN_CHUNK(CR, CZ, CN, NR, NZ, NN, S0)                                   \
    do {                                                                          \
        const size_t nb_ = (size_t)((S0) + CH) * G3;                              \
        _Pragma("unroll")                                                         \
        for (int k = 0; k < CH; k++) {                                            \
            NR[k] = __ldcg(gr + nb_ + (size_t)k * G3);                            \
            NZ[k] = __ldcg(gz + nb_ + (size_t)k * G3);                            \
            NN[k] = __ldcg(gn + nb_ + (size_t)k * G3);                            \
        }                                                                         \
        _Pragma("unroll")                                                         \
        for (int ss = 0; ss < CH; ss++) {                                         \
            const int p = ss & 1;                                                 \
            const ulonglong2* hp = (const ulonglong2*)(hbuf[p] + half * 32);      \
            ulonglong2 hq[8];                                                     \
            _Pragma("unroll")                                                     \
            for (int q = 0; q < 8; q++) hq[q] = hp[q];                            \
            const float hc05 = 0.5f * hcur;                                       \
            /* --- interleaved r/z/n dots: one dense FMA block --- */             \
            u64 a0 = 0, a1 = 0, b0 = 0, b1 = 0, c0 = bn_init, c1 = 0;             \
            _Pragma("unroll")                                                     \
            for (int q = 0; q < 8; q++) {                                         \
                a0 = fma2(wr[2 * q],     hq[q].x, a0);                            \
                b0 = fma2(wz[2 * q],     hq[q].x, b0);                            \
                c0 = fma2(wn[2 * q],     hq[q].x, c0);                            \
                a1 = fma2(wr[2 * q + 1], hq[q].y, a1);                            \
                b1 = fma2(wz[2 * q + 1], hq[q].y, b1);                            \
                c1 = fma2(wn[2 * q + 1], hq[q].y, c1);                            \
            }                                                                     \
            /* --- merged tail: 3 independent red+shfl chains overlap --- */      \
            float sr = red2(add2(a0, a1));                                        \
            float sz = red2(add2(b0, b1));                                        \
            float S_ = red2(add2(c0, c1));                                        \
            sr += __shfl_xor_sync(0xffffffffu, sr, 1);                            \
            sz += __shfl_xor_sync(0xffffffffu, sz, 1);                            \
            S_ += __shfl_xor_sync(0xffffffffu, S_, 1);                            \
            const float gnS = CN[ss] + S_;          /* before tr arrives */       \
            const float tr = tanhmu(sr + CR[ss]);                                 \
            const float tz = tanhmu(sz + CZ[ss]);                                 \
            const float A_ = fmaf(hc05, tz, hc05);                                \
            const float B_ = fmaf(-0.5f, tz, 0.5f);                               \
            const float n_ = tanhmu(fmaf(tr, S_, gnS));                           \
            const float hnew = fmaf(n_, B_, A_);                                  \
            hcur = hnew;                                                          \
            if (half) {                                                           \
                hbuf[p ^ 1][j] = hnew;                                            \
                g_hs[(size_t)((S0) + ss) * HID + j] = hnew;                       \
            }                                                                     \
            __syncthreads();                                                      \
        }                                                                         \
    } while (0)

__global__ __launch_bounds__(128, 1) void scan_kernel(const float* __restrict__ h0,
                                                      const float* __restrict__ w_hh,
                                                      const float* __restrict__ b_hh,
                                                      float* __restrict__ h_final) {
    __shared__ __align__(16) float hbuf[2][HID];

    const int tid  = threadIdx.x;
    const int w    = tid >> 5;
    const int lane = tid & 31;
    const int m    = lane >> 1;
    const int j    = w * 16 + m;
    const int half = lane & 1;               // 0: k 0..31, 1: k 32..63

    // Weight half-rows in registers, pre-halved (tanh-sigmoid + 2rS identity)
    u64 wr[16], wz[16], wn[16];
    {
        const u64 h05 = pack2(0.5f, 0.5f);
        const u64* pr = (const u64*)(w_hh + (size_t)j * HID)         + half * 16;
        const u64* pz = (const u64*)(w_hh + (size_t)(64 + j) * HID)  + half * 16;
        const u64* pn = (const u64*)(w_hh + (size_t)(128 + j) * HID) + half * 16;
#pragma unroll
        for (int k = 0; k < 16; k++) {
            wr[k] = mul2(pr[k], h05);
            wz[k] = mul2(pz[k], h05);
            wn[k] = mul2(pn[k], h05);
        }
    }
    const float bn = b_hh[128 + j];
    const u64 bn_init = half ? 0ULL : pack2(0.5f * bn, 0.0f);   // bn/2 into S

    if (tid < HID) hbuf[0][tid] = h0[tid];
    float hcur = h0[j];

    const float* gr = g_gi + j;
    const float* gz = g_gi + 64 + j;
    const float* gn = g_gi + 128 + j;

    float gAr[CH], gAz[CH], gAn[CH];
    float gBr[CH], gBz[CH], gBn[CH];
#pragma unroll
    for (int k = 0; k < CH; k++) {
        gAr[k] = __ldcg(gr + (size_t)k * G3);
        gAz[k] = __ldcg(gz + (size_t)k * G3);
        gAn[k] = __ldcg(gn + (size_t)k * G3);
    }
    __syncthreads();

#pragma unroll 1
    for (int s0 = 0; s0 < T_STEPS; s0 += 2 * CH) {
        SCAN_CHUNK(gAr, gAz, gAn, gBr, gBz, gBn, s0);
        SCAN_CHUNK(gBr, gBz, gBn, gAr, gAz, gAn, s0 + CH);
    }
    if (half) h_final[j] = hcur;
}

// =====================================================================
// Kernel 3: logits[t,o] = mask[o] ? hs[t,:]·w_out[o,:] + b_out[o] : -1e9
// =====================================================================
__global__ __launch_bounds__(256) void out_kernel(const float* __restrict__ w_out,
                                                  const float* __restrict__ b_out,
                                                  const int* __restrict__ mask,
                                                  float* __restrict__ out) {
    __shared__ float hs_sh[64][68];
    __shared__ float w_sh[64][68];

    const int tid = threadIdx.x;
    const int t0  = blockIdx.x * 64;
    const int o0  = blockIdx.y * 64;

#pragma unroll
    for (int q = 0; q < 4; q++) {
        int i  = tid + q * 256;
        int rr = i >> 4;
        int kq = i & 15;
        float4 v = *(const float4*)(g_hs + (size_t)(t0 + rr) * HID + kq * 4);
        hs_sh[kq * 4 + 0][rr] = v.x;
        hs_sh[kq * 4 + 1][rr] = v.y;
        hs_sh[kq * 4 + 2][rr] = v.z;
        hs_sh[kq * 4 + 3][rr] = v.w;
        float4 wv = *(const float4*)(w_out + (size_t)(o0 + rr) * HID + kq * 4);
        w_sh[kq * 4 + 0][rr] = wv.x;
        w_sh[kq * 4 + 1][rr] = wv.y;
        w_sh[kq * 4 + 2][rr] = wv.z;
        w_sh[kq * 4 + 3][rr] = wv.w;
    }
    __syncthreads();

    const int oo0 = (tid & 15) * 4;
    const int tt0 = (tid >> 4) * 4;

    float acc[4][4];
#pragma unroll
    for (int i = 0; i < 4; i++)
#pragma unroll
        for (int jj2 = 0; jj2 < 4; jj2++) acc[i][jj2] = 0.0f;

#pragma unroll
    for (int k = 0; k < 64; k++) {
        float4 a = *(const float4*)&hs_sh[k][tt0];
        float4 b = *(const float4*)&w_sh[k][oo0];
        float av[4] = {a.x, a.y, a.z, a.w};
        float bv[4] = {b.x, b.y, b.z, b.w};
#pragma unroll
        for (int i = 0; i < 4; i++)
#pragma unroll
            for (int jj2 = 0; jj2 < 4; jj2++) acc[i][jj2] += av[i] * bv[jj2];
    }

    float bo[4]; int mk[4];
#pragma unroll
    for (int jj2 = 0; jj2 < 4; jj2++) {
        int o = o0 + oo0 + jj2;
        bo[jj2] = b_out[o];
        mk[jj2] = mask[o];
    }
#pragma unroll
    for (int i = 0; i < 4; i++) {
        float r4[4];
#pragma unroll
        for (int jj2 = 0; jj2 < 4; jj2++) {
            float v = acc[i][jj2] + bo[jj2];
            r4[jj2] = (mk[jj2] == 0) ? -1000000000.0f : v;
        }
        float4 res = make_float4(r4[0], r4[1], r4[2], r4[3]);
        *(float4*)(out + (size_t)(t0 + tt0 + i) * JJ + o0 + oo0) = res;
    }
}

// =====================================================================
extern "C" void kernel_launch(void* const* d_in, const int* in_sizes, int n_in,
                              void* d_out, int out_size) {
    const float* states = (const float*)d_in[0];
    const float* h0     = (const float*)d_in[1];
    const float* w_ih   = (const float*)d_in[2];
    const float* w_hh   = (const float*)d_in[3];
    const float* b_ih   = (const float*)d_in[4];
    const float* b_hh   = (const float*)d_in[5];
    const float* w_out  = (const float*)d_in[6];
    const float* b_out  = (const float*)d_in[7];
    const int*   mask   = (const int*)d_in[8];
    float* out = (float*)d_out;

    gi_kernel<<<1024, 192>>>(states, w_ih, b_ih, b_hh);
    scan_kernel<<<1, 128>>>(h0, w_hh, b_hh, out + (size_t)T_STEPS * JJ);
    out_kernel<<<dim3(512, 16), 256>>>(w_out, b_out, mask, out);
}

// round 17
// speedup vs baseline: 1.4518x; 1.0321x over previous
#include <cuda_runtime.h>

#define T_STEPS 32768
#define DIM     256
#define HID     64
#define G3      192      // 3*HID
#define JJ      1024     // J*J
#define CH      4        // scan prefetch chunk (paired: 2*CH lookahead fits pad)

// Scratch (no runtime allocation allowed)
__device__ float g_gi[(T_STEPS + 2 * CH) * G3];   // padded for prefetch overrun
__device__ float g_hs[T_STEPS * HID];

typedef unsigned long long u64;

// ---------------- helpers ----------------
__device__ __forceinline__ u64 pack2(float lo, float hi) {
    u64 r; asm("mov.b64 %0, {%1, %2};" : "=l"(r) : "f"(lo), "f"(hi)); return r;
}
__device__ __forceinline__ void unpack2(u64 v, float& lo, float& hi) {
    asm("mov.b64 {%0, %1}, %2;" : "=f"(lo), "=f"(hi) : "l"(v));
}
__device__ __forceinline__ u64 fma2(u64 a, u64 b, u64 c) {
    u64 d; asm("fma.rn.f32x2 %0, %1, %2, %3;" : "=l"(d) : "l"(a), "l"(b), "l"(c)); return d;
}
__device__ __forceinline__ u64 add2(u64 a, u64 b) {
    u64 d; asm("add.rn.f32x2 %0, %1, %2;" : "=l"(d) : "l"(a), "l"(b)); return d;
}
__device__ __forceinline__ u64 mul2(u64 a, u64 b) {
    u64 d; asm("mul.rn.f32x2 %0, %1, %2;" : "=l"(d) : "l"(a), "l"(b)); return d;
}
__device__ __forceinline__ float red2(u64 v) { float a, b; unpack2(v, a, b); return a + b; }

__device__ __forceinline__ float tanhmu(float x){ float r; asm("tanh.approx.f32 %0, %1;" : "=f"(r) : "f"(x)); return r; }

// =====================================================================
// Kernel 1: gi precompute.
//   g < 128  (r,z rows): gi = 0.5 * (x·w_ih[g] + b_ih[g] + b_hh[g])   [tanh-sigmoid form]
//   g >= 128 (n rows)  : gi =        x·w_ih[g] + b_ih[g]
// =====================================================================
__global__ __launch_bounds__(192) void gi_kernel(const float* __restrict__ states,
                                                 const float* __restrict__ w_ih,
                                                 const float* __restrict__ b_ih,
                                                 const float* __restrict__ b_hh) {
    __shared__ float xs[32][36];
    const int tid = threadIdx.x;
    const int t0  = blockIdx.x * 32;

    u64 acc[16];
#pragma unroll
    for (int q = 0; q < 16; q++) acc[q] = 0ULL;

    const float* wrow = w_ih + (size_t)tid * DIM;

    for (int d0 = 0; d0 < DIM; d0 += 32) {
        __syncthreads();
        for (int i = tid; i < 1024; i += 192) {
            int dd = i & 31, tt = i >> 5;
            xs[dd][tt] = states[(size_t)(t0 + tt) * (DIM + 3) + d0 + dd];
        }
        __syncthreads();

        float wv[32];
#pragma unroll
        for (int dd = 0; dd < 32; dd++) wv[dd] = wrow[d0 + dd];

#pragma unroll
        for (int dd = 0; dd < 32; dd++) {
            u64 wp = pack2(wv[dd], wv[dd]);
            const float4* xr = (const float4*)xs[dd];
#pragma unroll
            for (int q = 0; q < 8; q++) {
                float4 v = xr[q];
                acc[2 * q + 0] = fma2(pack2(v.x, v.y), wp, acc[2 * q + 0]);
                acc[2 * q + 1] = fma2(pack2(v.z, v.w), wp, acc[2 * q + 1]);
            }
        }
    }

    const bool rz = (tid < 128);
    const float b = b_ih[tid] + (rz ? b_hh[tid] : 0.0f);
    const float s = rz ? 0.5f : 1.0f;
#pragma unroll
    for (int q = 0; q < 16; q++) {
        float a, c; unpack2(acc[q], a, c);
        g_gi[(size_t)(t0 + 2 * q + 0) * G3 + tid] = s * (a + b);
        g_gi[(size_t)(t0 + 2 * q + 1) * G3 + tid] = s * (c + b);
    }
}

// =====================================================================
// Kernel 2: sequential GRU scan. ONE block, 128 threads (4 warps).
// Lane pair (2m,2m+1) owns j = warp*16+m, k-halved. Interleaved r/z/n
// dots (one dense FMA block) -> merged tail (3 overlapping red/shfl
// chains). NEW vs R16:
//   - gi r/z values folded into even-lane accumulator INITS (removes
//     the post-shfl +CR/+CZ FADDs from the critical chain)
//   - zero-MOV accumulator inits replaced by q=0 mul2/folded-fma2
// tanh-sigmoid identity throughout; weights pre-halved.
// =====================================================================

#define SCAN_CHUNK(CR, CZ, CN, NR, NZ, NN, S0)                                   \
    do {                                                                          \
        const size_t nb_ = (size_t)((S0) + CH) * G3;                              \
        _Pragma("unroll")                                                         \
        for (int k = 0; k < CH; k++) {                                            \
            NR[k] = __ldcg(gr + nb_ + (size_t)k * G3);                            \
            NZ[k] = __ldcg(gz + nb_ + (size_t)k * G3);                            \
            NN[k] = __ldcg(gn + nb_ + (size_t)k * G3);                            \
        }                                                                         \
        /* hoisted even-lane init packs (alu pipe, off critical path) */          \
        u64 aI_[CH], bI_[CH];                                                     \
        _Pragma("unroll")                                                         \
        for (int k = 0; k < CH; k++) {                                            \
            aI_[k] = half ? 0ULL : pack2(CR[k], 0.0f);                            \
            bI_[k] = half ? 0ULL : pack2(CZ[k], 0.0f);                            \
        }                                                                         \
        _Pragma("unroll")                                                         \
        for (int ss = 0; ss < CH; ss++) {                                         \
            const int p = ss & 1;                                                 \
            const ulonglong2* hp = (const ulonglong2*)(hbuf[p] + half * 32);      \
            ulonglong2 hq[8];                                                     \
            _Pragma("unroll")                                                     \
            for (int q = 0; q < 8; q++) hq[q] = hp[q];                            \
            const float hc05 = 0.5f * hcur;                                       \
            /* --- interleaved r/z/n dots; inits folded into q=0 --- */           \
            u64 a0 = fma2(wr[0], hq[0].x, aI_[ss]);                               \
            u64 b0 = fma2(wz[0], hq[0].x, bI_[ss]);                               \
            u64 c0 = fma2(wn[0], hq[0].x, bn_init);                               \
            u64 a1 = mul2(wr[1], hq[0].y);                                        \
            u64 b1 = mul2(wz[1], hq[0].y);                                        \
            u64 c1 = mul2(wn[1], hq[0].y);                                        \
            _Pragma("unroll")                                                     \
            for (int q = 1; q < 8; q++) {                                         \
                a0 = fma2(wr[2 * q],     hq[q].x, a0);                            \
                b0 = fma2(wz[2 * q],     hq[q].x, b0);                            \
                c0 = fma2(wn[2 * q],     hq[q].x, c0);                            \
                a1 = fma2(wr[2 * q + 1], hq[q].y, a1);                            \
                b1 = fma2(wz[2 * q + 1], hq[q].y, b1);                            \
                c1 = fma2(wn[2 * q + 1], hq[q].y, c1);                            \
            }                                                                     \
            /* --- merged tail: 3 independent red+shfl chains overlap --- */      \
            float sr = red2(add2(a0, a1));                                        \
            float sz = red2(add2(b0, b1));                                        \
            float S_ = red2(add2(c0, c1));                                        \
            sr += __shfl_xor_sync(0xffffffffu, sr, 1);                            \
            sz += __shfl_xor_sync(0xffffffffu, sz, 1);                            \
            S_ += __shfl_xor_sync(0xffffffffu, S_, 1);                            \
            const float gnS = CN[ss] + S_;          /* before tr arrives */       \
            const float tr = tanhmu(sr);            /* CR already inside */       \
            const float tz = tanhmu(sz);            /* CZ already inside */       \
            const float A_ = fmaf(hc05, tz, hc05);                                \
            const float B_ = fmaf(-0.5f, tz, 0.5f);                               \
            const float n_ = tanhmu(fmaf(tr, S_, gnS));                           \
            const float hnew = fmaf(n_, B_, A_);                                  \
            hcur = hnew;                                                          \
            if (half) {                                                           \
                hbuf[p ^ 1][j] = hnew;                                            \
                g_hs[(size_t)((S0) + ss) * HID + j] = hnew;                       \
            }                                                                     \
            __syncthreads();                                                      \
        }                                                                         \
    } while (0)

__global__ __launch_bounds__(128, 1) void scan_kernel(const float* __restrict__ h0,
                                                      const float* __restrict__ w_hh,
                                                      const float* __restrict__ b_hh,
                                                      float* __restrict__ h_final) {
    __shared__ __align__(16) float hbuf[2][HID];

    const int tid  = threadIdx.x;
    const int w    = tid >> 5;
    const int lane = tid & 31;
    const int m    = lane >> 1;
    const int j    = w * 16 + m;
    const int half = lane & 1;               // 0: k 0..31, 1: k 32..63

    // Weight half-rows in registers, pre-halved (tanh-sigmoid + 2rS identity)
    u64 wr[16], wz[16], wn[16];
    {
        const u64 h05 = pack2(0.5f, 0.5f);
        const u64* pr = (const u64*)(w_hh + (size_t)j * HID)         + half * 16;
        const u64* pz = (const u64*)(w_hh + (size_t)(64 + j) * HID)  + half * 16;
        const u64* pn = (const u64*)(w_hh + (size_t)(128 + j) * HID) + half * 16;
#pragma unroll
        for (int k = 0; k < 16; k++) {
            wr[k] = mul2(pr[k], h05);
            wz[k] = mul2(pz[k], h05);
            wn[k] = mul2(pn[k], h05);
        }
    }
    const float bn = b_hh[128 + j];
    const u64 bn_init = half ? 0ULL : pack2(0.5f * bn, 0.0f);   // bn/2 into S

    if (tid < HID) hbuf[0][tid] = h0[tid];
    float hcur = h0[j];

    const float* gr = g_gi + j;
    const float* gz = g_gi + 64 + j;
    const float* gn = g_gi + 128 + j;

    float gAr[CH], gAz[CH], gAn[CH];
    float gBr[CH], gBz[CH], gBn[CH];
#pragma unroll
    for (int k = 0; k < CH; k++) {
        gAr[k] = __ldcg(gr + (size_t)k * G3);
        gAz[k] = __ldcg(gz + (size_t)k * G3);
        gAn[k] = __ldcg(gn + (size_t)k * G3);
    }
    __syncthreads();

#pragma unroll 1
    for (int s0 = 0; s0 < T_STEPS; s0 += 2 * CH) {
        SCAN_CHUNK(gAr, gAz, gAn, gBr, gBz, gBn, s0);
        SCAN_CHUNK(gBr, gBz, gBn, gAr, gAz, gAn, s0 + CH);
    }
    if (half) h_final[j] = hcur;
}

// =====================================================================
// Kernel 3: logits[t,o] = mask[o] ? hs[t,:]·w_out[o,:] + b_out[o] : -1e9
// =====================================================================
__global__ __launch_bounds__(256) void out_kernel(const float* __restrict__ w_out,
                                                  const float* __restrict__ b_out,
                                                  const int* __restrict__ mask,
                                                  float* __restrict__ out) {
    __shared__ float hs_sh[64][68];
    __shared__ float w_sh[64][68];

    const int tid = threadIdx.x;
    const int t0  = blockIdx.x * 64;
    const int o0  = blockIdx.y * 64;

#pragma unroll
    for (int q = 0; q < 4; q++) {
        int i  = tid + q * 256;
        int rr = i >> 4;
        int kq = i & 15;
        float4 v = *(const float4*)(g_hs + (size_t)(t0 + rr) * HID + kq * 4);
        hs_sh[kq * 4 + 0][rr] = v.x;
        hs_sh[kq * 4 + 1][rr] = v.y;
        hs_sh[kq * 4 + 2][rr] = v.z;
        hs_sh[kq * 4 + 3][rr] = v.w;
        float4 wv = *(const float4*)(w_out + (size_t)(o0 + rr) * HID + kq * 4);
        w_sh[kq * 4 + 0][rr] = wv.x;
        w_sh[kq * 4 + 1][rr] = wv.y;
        w_sh[kq * 4 + 2][rr] = wv.z;
        w_sh[kq * 4 + 3][rr] = wv.w;
    }
    __syncthreads();

    const int oo0 = (tid & 15) * 4;
    const int tt0 = (tid >> 4) * 4;

    float acc[4][4];
#pragma unroll
    for (int i = 0; i < 4; i++)
#pragma unroll
        for (int jj2 = 0; jj2 < 4; jj2++) acc[i][jj2] = 0.0f;

#pragma unroll
    for (int k = 0; k < 64; k++) {
        float4 a = *(const float4*)&hs_sh[k][tt0];
        float4 b = *(const float4*)&w_sh[k][oo0];
        float av[4] = {a.x, a.y, a.z, a.w};
        float bv[4] = {b.x, b.y, b.z, b.w};
#pragma unroll
        for (int i = 0; i < 4; i++)
#pragma unroll
            for (int jj2 = 0; jj2 < 4; jj2++) acc[i][jj2] += av[i] * bv[jj2];
    }

    float bo[4]; int mk[4];
#pragma unroll
    for (int jj2 = 0; jj2 < 4; jj2++) {
        int o = o0 + oo0 + jj2;
        bo[jj2] = b_out[o];
        mk[jj2] = mask[o];
    }
#pragma unroll
    for (int i = 0; i < 4; i++) {
        float r4[4];
#pragma unroll
        for (int jj2 = 0; jj2 < 4; jj2++) {
            float v = acc[i][jj2] + bo[jj2];
            r4[jj2] = (mk[jj2] == 0) ? -1000000000.0f : v;
        }
        float4 res = make_float4(r4[0], r4[1], r4[2], r4[3]);
        *(float4*)(out + (size_t)(t0 + tt0 + i) * JJ + o0 + oo0) = res;
    }
}

// =====================================================================
extern "C" void kernel_launch(void* const* d_in, const int* in_sizes, int n_in,
                              void* d_out, int out_size) {
    const float* states = (const float*)d_in[0];
    const float* h0     = (const float*)d_in[1];
    const float* w_ih   = (const float*)d_in[2];
    const float* w_hh   = (const float*)d_in[3];
    const float* b_ih   = (const float*)d_in[4];
    const float* b_hh   = (const float*)d_in[5];
    const float* w_out  = (const float*)d_in[6];
    const float* b_out  = (const float*)d_in[7];
    const int*   mask   = (const int*)d_in[8];
    float* out = (float*)d_out;

    gi_kernel<<<1024, 192>>>(states, w_ih, b_ih, b_hh);
    scan_kernel<<<1, 128>>>(h0, w_hh, b_hh, out + (size_t)T_STEPS * JJ);
    out_kernel<<<dim3(512, 16), 256>>>(w_out, b_out, mask, out);
}